// round 1
// baseline (speedup 1.0000x reference)
#include <cuda_runtime.h>
#include <cuda_bf16.h>
#include <cuda_fp8.h>
#include <cstdint>
#include <cstddef>

#define Hdim 4096
#define Tdim 8192

// ---------------- scratch (static device allocations; no cudaMalloc) ----------------
__device__ float          g_X[(size_t)Tdim * Hdim];          // residual / accumulator (f32)
__device__ __nv_bfloat16  g_A[(size_t)Tdim * Hdim];          // dequantized activations (bf16)
__device__ __nv_bfloat16  g_W[3ull * Hdim * Hdim];           // dequantized weights (bf16)

// ---------------- fp4/fp8 emulation helpers ----------------
// Round to nearest FP4 e2m1 magnitude, midpoints round UP (matches searchsorted side='right')
__device__ __forceinline__ float fp4_round(float v) {
    float a = fminf(fabsf(v), 6.0f);
    float r = (a < 0.25f) ? 0.0f :
              (a < 0.75f) ? 0.5f :
              (a < 1.25f) ? 1.0f :
              (a < 1.75f) ? 1.5f :
              (a < 2.5f)  ? 2.0f :
              (a < 3.5f)  ? 3.0f :
              (a < 5.0f)  ? 4.0f : 6.0f;
    return copysignf(r, v);
}

// Quantize one 16-element block: emulate scaled_fp4_quant, write dequantized q*sc as bf16.
__device__ __forceinline__ void quant16(const float (&v)[16], float gs, __nv_bfloat16* out) {
    float amax = 0.f;
    #pragma unroll
    for (int j = 0; j < 16; ++j) amax = fmaxf(amax, fabsf(v[j]));
    float scf = fminf(amax / 6.0f * gs, 448.0f);
    float sc = (float)__nv_fp8_e4m3(scf);   // e4m3 RN rounding of the block scale
    __nv_bfloat16 q[16];
    if (sc > 0.f) {
        #pragma unroll
        for (int j = 0; j < 16; ++j)
            q[j] = __float2bfloat16(fp4_round(v[j] * gs / sc) * sc);  // exact in bf16
    } else {
        #pragma unroll
        for (int j = 0; j < 16; ++j) q[j] = __float2bfloat16(0.f);
    }
    uint4* o = reinterpret_cast<uint4*>(out);
    const uint4* qi = reinterpret_cast<const uint4*>(q);
    o[0] = qi[0];
    o[1] = qi[1];
}

// block-wide sum-of-squares -> rsqrt(mean + eps). blockDim.x == 256.
__device__ __forceinline__ float block_rms(float ss) {
    #pragma unroll
    for (int o = 16; o; o >>= 1) ss += __shfl_xor_sync(0xffffffffu, ss, o);
    __shared__ float red[8];
    __shared__ float s_rinv;
    int t = threadIdx.x;
    if ((t & 31) == 0) red[t >> 5] = ss;
    __syncthreads();
    if (t == 0) {
        float tot = 0.f;
        #pragma unroll
        for (int i = 0; i < 8; ++i) tot += red[i];
        s_rinv = rsqrtf(tot / (float)Hdim + 1e-6f);
    }
    __syncthreads();
    return s_rinv;
}

// ---------------- kernels ----------------

// x = relu(hidden); g_X = x; y = rmsnorm(x, nw); g_A = dequant(quant(y, gs))
__global__ void k_relu_normquant(const float* __restrict__ hs,
                                 const float* __restrict__ nw,
                                 const float* __restrict__ gsp) {
    int row = blockIdx.x;
    int t = threadIdx.x;
    const float4* src = reinterpret_cast<const float4*>(hs + (size_t)row * Hdim);
    float4* xdst = reinterpret_cast<float4*>(g_X + (size_t)row * Hdim);
    float v[16];
    float ss = 0.f;
    #pragma unroll
    for (int i = 0; i < 4; ++i) {
        float4 f = src[t * 4 + i];
        f.x = fmaxf(f.x, 0.f); f.y = fmaxf(f.y, 0.f);
        f.z = fmaxf(f.z, 0.f); f.w = fmaxf(f.w, 0.f);
        xdst[t * 4 + i] = f;
        v[i * 4 + 0] = f.x; v[i * 4 + 1] = f.y; v[i * 4 + 2] = f.z; v[i * 4 + 3] = f.w;
        ss += f.x * f.x + f.y * f.y + f.z * f.z + f.w * f.w;
    }
    float rinv = block_rms(ss);
    const float4* nwv = reinterpret_cast<const float4*>(nw);
    #pragma unroll
    for (int i = 0; i < 4; ++i) {
        float4 g = nwv[t * 4 + i];
        v[i * 4 + 0] *= rinv * g.x; v[i * 4 + 1] *= rinv * g.y;
        v[i * 4 + 2] *= rinv * g.z; v[i * 4 + 3] *= rinv * g.w;
    }
    quant16(v, gsp[0], g_A + (size_t)row * Hdim + t * 16);
}

// y = rmsnorm(g_X[row], nw); g_A = dequant(quant(y, gs))
__global__ void k_normquant(const float* __restrict__ nw,
                            const float* __restrict__ gsp) {
    int row = blockIdx.x;
    int t = threadIdx.x;
    const float4* src = reinterpret_cast<const float4*>(g_X + (size_t)row * Hdim);
    float v[16];
    float ss = 0.f;
    #pragma unroll
    for (int i = 0; i < 4; ++i) {
        float4 f = src[t * 4 + i];
        v[i * 4 + 0] = f.x; v[i * 4 + 1] = f.y; v[i * 4 + 2] = f.z; v[i * 4 + 3] = f.w;
        ss += f.x * f.x + f.y * f.y + f.z * f.z + f.w * f.w;
    }
    float rinv = block_rms(ss);
    const float4* nwv = reinterpret_cast<const float4*>(nw);
    #pragma unroll
    for (int i = 0; i < 4; ++i) {
        float4 g = nwv[t * 4 + i];
        v[i * 4 + 0] *= rinv * g.x; v[i * 4 + 1] *= rinv * g.y;
        v[i * 4 + 2] *= rinv * g.z; v[i * 4 + 3] *= rinv * g.w;
    }
    quant16(v, gsp[0], g_A + (size_t)row * Hdim + t * 16);
}

// Quantize all 3 weight matrices -> dequantized bf16. blockIdx.x in [0, 3*Hdim)
__global__ void k_quantw(const float* __restrict__ w,
                         const float* __restrict__ wgs) {
    int bid = blockIdx.x;
    int i = bid >> 12;                   // / 4096
    size_t off = (size_t)bid * Hdim;     // (i*H + row) * H
    const float4* src = reinterpret_cast<const float4*>(w + off);
    float gs = wgs[i];
    int t = threadIdx.x;
    float v[16];
    #pragma unroll
    for (int j = 0; j < 4; ++j) {
        float4 f = src[t * 4 + j];
        v[j * 4 + 0] = f.x; v[j * 4 + 1] = f.y; v[j * 4 + 2] = f.z; v[j * 4 + 3] = f.w;
    }
    quant16(v, gs, g_W + off + t * 16);
}

// out = rmsnorm(g_X[row], nw) as f32
__global__ void k_out(const float* __restrict__ nw, float* __restrict__ out) {
    int row = blockIdx.x;
    int t = threadIdx.x;
    const float4* src = reinterpret_cast<const float4*>(g_X + (size_t)row * Hdim);
    float4 vv[4];
    float ss = 0.f;
    #pragma unroll
    for (int i = 0; i < 4; ++i) {
        float4 f = src[t * 4 + i];
        vv[i] = f;
        ss += f.x * f.x + f.y * f.y + f.z * f.z + f.w * f.w;
    }
    float rinv = block_rms(ss);
    const float4* nwv = reinterpret_cast<const float4*>(nw);
    float4* dst = reinterpret_cast<float4*>(out + (size_t)row * Hdim);
    #pragma unroll
    for (int i = 0; i < 4; ++i) {
        float4 g = nwv[t * 4 + i];
        float4 r;
        r.x = vv[i].x * rinv * g.x; r.y = vv[i].y * rinv * g.y;
        r.z = vv[i].z * rinv * g.z; r.w = vv[i].w * rinv * g.w;
        dst[t * 4 + i] = r;
    }
}

// ---------------- bf16 GEMM: X[M,N] += alpha * A[M,K] @ B[N,K]^T ----------------
#define BM 128
#define BN 128
#define BK 32
#define SSTR 40                      // bf16 elems per smem row (BK + 8 skew, 80B => conflict-free ldmatrix)
#define STAGE_BYTES (BM * SSTR * 2)  // 10240 B per stage per operand

__device__ __forceinline__ void cp16(uint32_t s, const void* g) {
    asm volatile("cp.async.cg.shared.global [%0], [%1], 16;\n" :: "r"(s), "l"(g));
}
__device__ __forceinline__ void ldmx4(uint32_t (&r)[4], uint32_t addr) {
    asm volatile("ldmatrix.sync.aligned.m8n8.x4.shared.b16 {%0,%1,%2,%3}, [%4];\n"
                 : "=r"(r[0]), "=r"(r[1]), "=r"(r[2]), "=r"(r[3]) : "r"(addr));
}
__device__ __forceinline__ void mma16816(float (&d)[4], const uint32_t (&a)[4],
                                         uint32_t b0, uint32_t b1) {
    asm volatile("mma.sync.aligned.m16n8k16.row.col.f32.bf16.bf16.f32 "
                 "{%0,%1,%2,%3}, {%4,%5,%6,%7}, {%8,%9}, {%0,%1,%2,%3};\n"
                 : "+f"(d[0]), "+f"(d[1]), "+f"(d[2]), "+f"(d[3])
                 : "r"(a[0]), "r"(a[1]), "r"(a[2]), "r"(a[3]), "r"(b0), "r"(b1));
}

__global__ __launch_bounds__(256, 2)
void k_gemm(int wi, const float* __restrict__ agp, const float* __restrict__ wgp) {
    __shared__ __nv_bfloat16 sA[2][BM * SSTR];
    __shared__ __nv_bfloat16 sB[2][BN * SSTR];

    const __nv_bfloat16* A = g_A;
    const __nv_bfloat16* B = g_W + (size_t)wi * Hdim * Hdim;
    const int K = Hdim, N = Hdim;

    int tid = threadIdx.x;
    int bm = blockIdx.y, bn = blockIdx.x;

    uint32_t sAb = (uint32_t)__cvta_generic_to_shared(&sA[0][0]);
    uint32_t sBb = (uint32_t)__cvta_generic_to_shared(&sB[0][0]);

    // ---- gmem -> smem mapping: 256 threads x 2 iters, 16B each
    int lr = tid >> 2;            // row 0..63 (+64 on iter 1)
    int lc = (tid & 3) * 8;       // k-chunk within BK
    const __nv_bfloat16* gA0 = A + (size_t)(bm * BM + lr) * K + lc;
    const __nv_bfloat16* gB0 = B + (size_t)(bn * BN + lr) * K + lc;

    // ---- warp / mma mapping (8 warps as 4x2; warp tile 32x64)
    int lane = tid & 31;
    int wr = (tid >> 6);          // tid>>5 >>1 : 0..3
    int wc = (tid >> 5) & 1;      // 0..1
    int aRow = wr * 32 + (lane & 15);
    int aCol = (lane >> 4) * 8;
    int bRow = wc * 64 + (lane & 7) + ((lane >> 4) & 1) * 8;
    int bCol = ((lane >> 3) & 1) * 8;

    float acc[2][8][4];
    #pragma unroll
    for (int mi = 0; mi < 2; ++mi)
        #pragma unroll
        for (int ni = 0; ni < 8; ++ni)
            #pragma unroll
            for (int j = 0; j < 4; ++j) acc[mi][ni][j] = 0.f;

    const int nk = K / BK;   // 128

    // prologue: stage 0
    {
        #pragma unroll
        for (int it = 0; it < 2; ++it) {
            int r = lr + it * 64;
            cp16(sAb + (r * SSTR + lc) * 2, gA0 + (size_t)(it * 64) * K);
            cp16(sBb + (r * SSTR + lc) * 2, gB0 + (size_t)(it * 64) * K);
        }
        asm volatile("cp.async.commit_group;\n");
    }

    #pragma unroll 1
    for (int kt = 0; kt < nk; ++kt) {
        int cur = kt & 1;
        if (kt + 1 < nk) {
            int s = cur ^ 1;
            int k0 = (kt + 1) * BK;
            #pragma unroll
            for (int it = 0; it < 2; ++it) {
                int r = lr + it * 64;
                cp16(sAb + s * STAGE_BYTES + (r * SSTR + lc) * 2,
                     gA0 + (size_t)(it * 64) * K + k0);
                cp16(sBb + s * STAGE_BYTES + (r * SSTR + lc) * 2,
                     gB0 + (size_t)(it * 64) * K + k0);
            }
            asm volatile("cp.async.commit_group;\n");
            asm volatile("cp.async.wait_group 1;\n" ::: "memory");
        } else {
            asm volatile("cp.async.wait_group 0;\n" ::: "memory");
        }
        __syncthreads();

        uint32_t aBase = sAb + cur * STAGE_BYTES;
        uint32_t bBase = sBb + cur * STAGE_BYTES;
        #pragma unroll
        for (int kk = 0; kk < BK; kk += 16) {
            uint32_t a[2][4], b[4][4];
            #pragma unroll
            for (int mi = 0; mi < 2; ++mi)
                ldmx4(a[mi], aBase + ((aRow + mi * 16) * SSTR + kk + aCol) * 2);
            #pragma unroll
            for (int ng = 0; ng < 4; ++ng)
                ldmx4(b[ng], bBase + ((bRow + ng * 16) * SSTR + kk + bCol) * 2);
            #pragma unroll
            for (int mi = 0; mi < 2; ++mi)
                #pragma unroll
                for (int ni = 0; ni < 8; ++ni)
                    mma16816(acc[mi][ni], a[mi],
                             b[ni >> 1][(ni & 1) * 2], b[ni >> 1][(ni & 1) * 2 + 1]);
        }
        __syncthreads();
    }

    // epilogue: X += alpha * acc  (residual add fused; X read-modify-write)
    float alpha = 1.0f / (wgp[0] * agp[0]);
    float* C = g_X;
    #pragma unroll
    for (int mi = 0; mi < 2; ++mi) {
        #pragma unroll
        for (int ni = 0; ni < 8; ++ni) {
            int row = bm * BM + wr * 32 + mi * 16 + (lane >> 2);
            int col = bn * BN + wc * 64 + ni * 8 + (lane & 3) * 2;
            float2* p0 = reinterpret_cast<float2*>(&C[(size_t)row * N + col]);
            float2 c0 = *p0;
            c0.x += alpha * acc[mi][ni][0];
            c0.y += alpha * acc[mi][ni][1];
            *p0 = c0;
            float2* p1 = reinterpret_cast<float2*>(&C[(size_t)(row + 8) * N + col]);
            float2 c1 = *p1;
            c1.x += alpha * acc[mi][ni][2];
            c1.y += alpha * acc[mi][ni][3];
            *p1 = c1;
        }
    }
}

// ---------------- launch ----------------
extern "C" void kernel_launch(void* const* d_in, const int* in_sizes, int n_in,
                              void* d_out, int out_size) {
    const float* hs  = (const float*)d_in[0];  // [T, H]
    const float* nw  = (const float*)d_in[1];  // [4, H]
    const float* w   = (const float*)d_in[2];  // [3, H, H]
    const float* ags = (const float*)d_in[3];  // [3]
    const float* wgs = (const float*)d_in[4];  // [3]
    float* out = (float*)d_out;                // [T, H]

    k_quantw<<<3 * Hdim, 256>>>(w, wgs);
    k_relu_normquant<<<Tdim, 256>>>(hs, nw, ags);

    dim3 gg(Hdim / BN, Tdim / BM);
    for (int i = 0; i < 3; ++i) {
        k_gemm<<<gg, 256>>>(i, ags + i, wgs + i);
        if (i < 2) k_normquant<<<Tdim, 256>>>(nw + (size_t)(i + 1) * Hdim, ags + i + 1);
    }
    k_out<<<Tdim, 256>>>(nw + 3 * Hdim, out);
}

// round 3
// speedup vs baseline: 1.4176x; 1.4176x over previous
#include <cuda_runtime.h>
#include <cuda_bf16.h>
#include <cuda_fp8.h>
#include <cstdint>
#include <cstddef>

#define Hdim 4096
#define Tdim 8192

// ---------------- scratch (static device allocations; no cudaMalloc) ----------------
__device__ float          g_X[(size_t)Tdim * Hdim];          // residual / accumulator (f32)
__device__ __nv_bfloat16  g_A[(size_t)Tdim * Hdim];          // dequantized activations (bf16)
__device__ __nv_bfloat16  g_W[3ull * Hdim * Hdim];           // dequantized weights (bf16)

// ---------------- fp4/fp8 emulation helpers ----------------
__device__ __forceinline__ float fp4_round(float v) {
    float a = fminf(fabsf(v), 6.0f);
    float r = (a < 0.25f) ? 0.0f :
              (a < 0.75f) ? 0.5f :
              (a < 1.25f) ? 1.0f :
              (a < 1.75f) ? 1.5f :
              (a < 2.5f)  ? 2.0f :
              (a < 3.5f)  ? 3.0f :
              (a < 5.0f)  ? 4.0f : 6.0f;
    return copysignf(r, v);
}

__device__ __forceinline__ void quant16(const float (&v)[16], float gs, __nv_bfloat16* out) {
    float amax = 0.f;
    #pragma unroll
    for (int j = 0; j < 16; ++j) amax = fmaxf(amax, fabsf(v[j]));
    float scf = fminf(amax / 6.0f * gs, 448.0f);
    float sc = (float)__nv_fp8_e4m3(scf);   // e4m3 RN rounding of the block scale
    __nv_bfloat16 q[16];
    if (sc > 0.f) {
        float t = gs / sc;                   // one divide per 16 elems
        #pragma unroll
        for (int j = 0; j < 16; ++j)
            q[j] = __float2bfloat16(fp4_round(v[j] * t) * sc);  // exact in bf16
    } else {
        #pragma unroll
        for (int j = 0; j < 16; ++j) q[j] = __float2bfloat16(0.f);
    }
    uint4* o = reinterpret_cast<uint4*>(out);
    const uint4* qi = reinterpret_cast<const uint4*>(q);
    o[0] = qi[0];
    o[1] = qi[1];
}

__device__ __forceinline__ float block_rms(float ss) {
    #pragma unroll
    for (int o = 16; o; o >>= 1) ss += __shfl_xor_sync(0xffffffffu, ss, o);
    __shared__ float red[8];
    __shared__ float s_rinv;
    int t = threadIdx.x;
    if ((t & 31) == 0) red[t >> 5] = ss;
    __syncthreads();
    if (t == 0) {
        float tot = 0.f;
        #pragma unroll
        for (int i = 0; i < 8; ++i) tot += red[i];
        s_rinv = rsqrtf(tot / (float)Hdim + 1e-6f);
    }
    __syncthreads();
    return s_rinv;
}

// ---------------- aux kernels ----------------
__global__ void k_relu_normquant(const float* __restrict__ hs,
                                 const float* __restrict__ nw,
                                 const float* __restrict__ gsp) {
    int row = blockIdx.x;
    int t = threadIdx.x;
    const float4* src = reinterpret_cast<const float4*>(hs + (size_t)row * Hdim);
    float4* xdst = reinterpret_cast<float4*>(g_X + (size_t)row * Hdim);
    float v[16];
    float ss = 0.f;
    #pragma unroll
    for (int i = 0; i < 4; ++i) {
        float4 f = src[t * 4 + i];
        f.x = fmaxf(f.x, 0.f); f.y = fmaxf(f.y, 0.f);
        f.z = fmaxf(f.z, 0.f); f.w = fmaxf(f.w, 0.f);
        xdst[t * 4 + i] = f;
        v[i * 4 + 0] = f.x; v[i * 4 + 1] = f.y; v[i * 4 + 2] = f.z; v[i * 4 + 3] = f.w;
        ss += f.x * f.x + f.y * f.y + f.z * f.z + f.w * f.w;
    }
    float rinv = block_rms(ss);
    const float4* nwv = reinterpret_cast<const float4*>(nw);
    #pragma unroll
    for (int i = 0; i < 4; ++i) {
        float4 g = nwv[t * 4 + i];
        v[i * 4 + 0] *= rinv * g.x; v[i * 4 + 1] *= rinv * g.y;
        v[i * 4 + 2] *= rinv * g.z; v[i * 4 + 3] *= rinv * g.w;
    }
    quant16(v, gsp[0], g_A + (size_t)row * Hdim + t * 16);
}

__global__ void k_normquant(const float* __restrict__ nw,
                            const float* __restrict__ gsp) {
    int row = blockIdx.x;
    int t = threadIdx.x;
    const float4* src = reinterpret_cast<const float4*>(g_X + (size_t)row * Hdim);
    float v[16];
    float ss = 0.f;
    #pragma unroll
    for (int i = 0; i < 4; ++i) {
        float4 f = src[t * 4 + i];
        v[i * 4 + 0] = f.x; v[i * 4 + 1] = f.y; v[i * 4 + 2] = f.z; v[i * 4 + 3] = f.w;
        ss += f.x * f.x + f.y * f.y + f.z * f.z + f.w * f.w;
    }
    float rinv = block_rms(ss);
    const float4* nwv = reinterpret_cast<const float4*>(nw);
    #pragma unroll
    for (int i = 0; i < 4; ++i) {
        float4 g = nwv[t * 4 + i];
        v[i * 4 + 0] *= rinv * g.x; v[i * 4 + 1] *= rinv * g.y;
        v[i * 4 + 2] *= rinv * g.z; v[i * 4 + 3] *= rinv * g.w;
    }
    quant16(v, gsp[0], g_A + (size_t)row * Hdim + t * 16);
}

__global__ void k_quantw(const float* __restrict__ w,
                         const float* __restrict__ wgs) {
    int bid = blockIdx.x;
    int i = bid >> 12;
    size_t off = (size_t)bid * Hdim;
    const float4* src = reinterpret_cast<const float4*>(w + off);
    float gs = wgs[i];
    int t = threadIdx.x;
    float v[16];
    #pragma unroll
    for (int j = 0; j < 4; ++j) {
        float4 f = src[t * 4 + j];
        v[j * 4 + 0] = f.x; v[j * 4 + 1] = f.y; v[j * 4 + 2] = f.z; v[j * 4 + 3] = f.w;
    }
    quant16(v, gs, g_W + off + t * 16);
}

__global__ void k_out(const float* __restrict__ nw, float* __restrict__ out) {
    int row = blockIdx.x;
    int t = threadIdx.x;
    const float4* src = reinterpret_cast<const float4*>(g_X + (size_t)row * Hdim);
    float4 vv[4];
    float ss = 0.f;
    #pragma unroll
    for (int i = 0; i < 4; ++i) {
        float4 f = src[t * 4 + i];
        vv[i] = f;
        ss += f.x * f.x + f.y * f.y + f.z * f.z + f.w * f.w;
    }
    float rinv = block_rms(ss);
    const float4* nwv = reinterpret_cast<const float4*>(nw);
    float4* dst = reinterpret_cast<float4*>(out + (size_t)row * Hdim);
    #pragma unroll
    for (int i = 0; i < 4; ++i) {
        float4 g = nwv[t * 4 + i];
        float4 r;
        r.x = vv[i].x * rinv * g.x; r.y = vv[i].y * rinv * g.y;
        r.z = vv[i].z * rinv * g.z; r.w = vv[i].w * rinv * g.w;
        dst[t * 4 + i] = r;
    }
}

// ======== mma.sync bf16 GEMM: X[M,N] += alpha * A[M,K] @ B[N,K]^T ========
// Tile 128x128xBK64, 3-stage cp.async pipeline, SW128-swizzled smem,
// 8 warps as 2x4 (warp tile 64x32), 2 CTAs/SM.
#define GBM 128
#define GBN 128
#define GBK 64
#define NSTAGE 3
#define TILE_B (GBM * 128)             // 16384 B (one operand, one stage)
#define STAGE_B (2 * TILE_B)           // 32768
#define GEMM_SMEM (NSTAGE * STAGE_B)   // 98304

__device__ __forceinline__ void cp16(uint32_t s, const void* g) {
    asm volatile("cp.async.cg.shared.global [%0], [%1], 16;\n" :: "r"(s), "l"(g));
}
__device__ __forceinline__ void ldmx4(uint32_t (&r)[4], uint32_t addr) {
    asm volatile("ldmatrix.sync.aligned.m8n8.x4.shared.b16 {%0,%1,%2,%3}, [%4];\n"
                 : "=r"(r[0]), "=r"(r[1]), "=r"(r[2]), "=r"(r[3]) : "r"(addr));
}
__device__ __forceinline__ void mma16816(float (&d)[4], const uint32_t (&a)[4],
                                         uint32_t b0, uint32_t b1) {
    asm volatile("mma.sync.aligned.m16n8k16.row.col.f32.bf16.bf16.f32 "
                 "{%0,%1,%2,%3}, {%4,%5,%6,%7}, {%8,%9}, {%0,%1,%2,%3};\n"
                 : "+f"(d[0]), "+f"(d[1]), "+f"(d[2]), "+f"(d[3])
                 : "r"(a[0]), "r"(a[1]), "r"(a[2]), "r"(a[3]), "r"(b0), "r"(b1));
}

__global__ __launch_bounds__(256, 2)
void k_gemm(int wi, const float* __restrict__ agp, const float* __restrict__ wgp) {
    extern __shared__ __align__(1024) char smem[];
    const uint32_t sbase = (uint32_t)__cvta_generic_to_shared(smem);

    const int tid = threadIdx.x;
    const int lane = tid & 31;
    const int wid = tid >> 5;
    const int wr = wid >> 2;            // 0..1  (64 rows each)
    const int wc = wid & 3;             // 0..3  (32 cols each)
    const int bm = blockIdx.y, bn = blockIdx.x;
    const int K = Hdim, N = Hdim;

    const __nv_bfloat16* Ag = g_A + (size_t)(bm * GBM) * K;
    const __nv_bfloat16* Bg = g_W + (size_t)wi * Hdim * Hdim + (size_t)(bn * GBN) * K;

    // ---- gmem->smem mapping: tid -> (row r0 + 32i, 16B segment), SW128 swizzle
    const int r0 = tid >> 3;                        // 0..31
    const int seg = tid & 7;                        // 16B segment in 128B row
    const uint32_t swoff = (uint32_t)(r0 * 128) + (uint32_t)((seg * 16) ^ ((r0 & 7) << 4));
    const __nv_bfloat16* gA = Ag + (size_t)r0 * K + seg * 8;
    const __nv_bfloat16* gB = Bg + (size_t)r0 * K + seg * 8;

    // ---- ldmatrix address precompute (swizzle XOR folded)
    // A: row = wr*64 + mi*16 + (lane&15); colbyte = kk*2 + (lane>>4)*16
    const uint32_t aRowB = (uint32_t)((wr * 64 + (lane & 15)) * 128);
    const uint32_t aXor = (uint32_t)((lane & 7) << 4);
    const uint32_t aColB = (uint32_t)((lane >> 4) * 16);
    // B: nrow = wc*32 + ng*16 + (lane&7) + ((lane>>4)&1)*8; colbyte = kk*2 + ((lane>>3)&1)*16
    const uint32_t bRowB = (uint32_t)((wc * 32 + (lane & 7) + ((lane >> 4) & 1) * 8) * 128);
    const uint32_t bXor = aXor;
    const uint32_t bColB = (uint32_t)(((lane >> 3) & 1) * 16);

    float acc[4][4][4];
    #pragma unroll
    for (int mi = 0; mi < 4; ++mi)
        #pragma unroll
        for (int ni = 0; ni < 4; ++ni)
            #pragma unroll
            for (int j = 0; j < 4; ++j) acc[mi][ni][j] = 0.f;

    const int nk = K / GBK;   // 64

    // stage loader
    auto load_stage = [&](int s, int kt) {
        uint32_t stA = sbase + s * STAGE_B;
        uint32_t stB = stA + TILE_B;
        const __nv_bfloat16* pA = gA + kt * GBK;
        const __nv_bfloat16* pB = gB + kt * GBK;
        #pragma unroll
        for (int i = 0; i < 4; ++i)
            cp16(stA + swoff + i * 4096, pA + (size_t)(i * 32) * K);
        #pragma unroll
        for (int i = 0; i < 4; ++i)
            cp16(stB + swoff + i * 4096, pB + (size_t)(i * 32) * K);
        asm volatile("cp.async.commit_group;\n");
    };

    load_stage(0, 0);
    load_stage(1, 1);

    int s = 0;
    #pragma unroll 1
    for (int kt = 0; kt < nk; ++kt) {
        if (kt == nk - 1) asm volatile("cp.async.wait_group 0;\n" ::: "memory");
        else              asm volatile("cp.async.wait_group 1;\n" ::: "memory");
        __syncthreads();

        uint32_t stA = sbase + s * STAGE_B;
        uint32_t stB = stA + TILE_B;
        #pragma unroll
        for (int kk = 0; kk < GBK; kk += 16) {
            uint32_t b[2][4];
            #pragma unroll
            for (int ng = 0; ng < 2; ++ng)
                ldmx4(b[ng], stB + bRowB + ng * 2048 + ((kk * 2 + bColB) ^ bXor));
            #pragma unroll
            for (int mi = 0; mi < 4; ++mi) {
                uint32_t a[4];
                ldmx4(a, stA + aRowB + mi * 2048 + ((kk * 2 + aColB) ^ aXor));
                #pragma unroll
                for (int ni = 0; ni < 4; ++ni)
                    mma16816(acc[mi][ni], a,
                             b[ni >> 1][(ni & 1) * 2], b[ni >> 1][(ni & 1) * 2 + 1]);
            }
        }
        __syncthreads();
        if (kt + 2 < nk) load_stage((kt + 2 == 2) ? 2 : ((kt + 2) % 3), kt + 2);
        if (++s == 3) s = 0;
    }

    // epilogue: X += alpha * acc  (fused residual add)
    const float alpha = 1.0f / (wgp[0] * agp[0]);
    float* C = g_X;
    #pragma unroll
    for (int mi = 0; mi < 4; ++mi) {
        #pragma unroll
        for (int ni = 0; ni < 4; ++ni) {
            int row = bm * GBM + wr * 64 + mi * 16 + (lane >> 2);
            int col = bn * GBN + wc * 32 + ni * 8 + (lane & 3) * 2;
            float2* p0 = reinterpret_cast<float2*>(&C[(size_t)row * N + col]);
            float2 c0 = *p0;
            c0.x += alpha * acc[mi][ni][0];
            c0.y += alpha * acc[mi][ni][1];
            *p0 = c0;
            float2* p1 = reinterpret_cast<float2*>(&C[(size_t)(row + 8) * N + col]);
            float2 c1 = *p1;
            c1.x += alpha * acc[mi][ni][2];
            c1.y += alpha * acc[mi][ni][3];
            *p1 = c1;
        }
    }
}

// ---------------- launch ----------------
extern "C" void kernel_launch(void* const* d_in, const int* in_sizes, int n_in,
                              void* d_out, int out_size) {
    const float* hs  = (const float*)d_in[0];  // [T, H]
    const float* nw  = (const float*)d_in[1];  // [4, H]
    const float* w   = (const float*)d_in[2];  // [3, H, H]
    const float* ags = (const float*)d_in[3];  // [3]
    const float* wgs = (const float*)d_in[4];  // [3]
    float* out = (float*)d_out;                // [T, H]

    cudaFuncSetAttribute(k_gemm, cudaFuncAttributeMaxDynamicSharedMemorySize, GEMM_SMEM);

    k_quantw<<<3 * Hdim, 256>>>(w, wgs);
    k_relu_normquant<<<Tdim, 256>>>(hs, nw, ags);

    dim3 gg(Hdim / GBN, Tdim / GBM);   // (32, 64)
    for (int i = 0; i < 3; ++i) {
        k_gemm<<<gg, 256, GEMM_SMEM>>>(i, ags + i, wgs + i);
        if (i < 2) k_normquant<<<Tdim, 256>>>(nw + (size_t)(i + 1) * Hdim, ags + i + 1);
    }
    k_out<<<Tdim, 256>>>(nw + 3 * Hdim, out);
}

// round 4
// speedup vs baseline: 1.4353x; 1.0124x over previous
#include <cuda_runtime.h>
#include <cuda_bf16.h>
#include <cuda_fp8.h>
#include <cstdint>
#include <cstddef>

#define Hdim 4096
#define Tdim 8192

// ---------------- scratch (static device allocations; no cudaMalloc) ----------------
__device__ float          g_X[(size_t)Tdim * Hdim];          // residual / accumulator (f32)
__device__ __nv_bfloat16  g_A[(size_t)Tdim * Hdim];          // dequantized activations (bf16)
__device__ __nv_bfloat16  g_W[3ull * Hdim * Hdim];           // dequantized weights (bf16)

// ---------------- fp4/fp8 emulation helpers ----------------
__device__ __forceinline__ float fp4_round(float v) {
    float a = fminf(fabsf(v), 6.0f);
    float r = (a < 0.25f) ? 0.0f :
              (a < 0.75f) ? 0.5f :
              (a < 1.25f) ? 1.0f :
              (a < 1.75f) ? 1.5f :
              (a < 2.5f)  ? 2.0f :
              (a < 3.5f)  ? 3.0f :
              (a < 5.0f)  ? 4.0f : 6.0f;
    return copysignf(r, v);
}

__device__ __forceinline__ void quant16(const float (&v)[16], float gs, __nv_bfloat16* out) {
    float amax = 0.f;
    #pragma unroll
    for (int j = 0; j < 16; ++j) amax = fmaxf(amax, fabsf(v[j]));
    float scf = fminf(amax / 6.0f * gs, 448.0f);
    float sc = (float)__nv_fp8_e4m3(scf);   // e4m3 RN rounding of the block scale
    __nv_bfloat16 q[16];
    if (sc > 0.f) {
        float t = gs / sc;                   // one divide per 16 elems
        #pragma unroll
        for (int j = 0; j < 16; ++j)
            q[j] = __float2bfloat16(fp4_round(v[j] * t) * sc);  // exact in bf16
    } else {
        #pragma unroll
        for (int j = 0; j < 16; ++j) q[j] = __float2bfloat16(0.f);
    }
    uint4* o = reinterpret_cast<uint4*>(out);
    const uint4* qi = reinterpret_cast<const uint4*>(q);
    o[0] = qi[0];
    o[1] = qi[1];
}

__device__ __forceinline__ float block_rms(float ss) {
    #pragma unroll
    for (int o = 16; o; o >>= 1) ss += __shfl_xor_sync(0xffffffffu, ss, o);
    __shared__ float red[8];
    __shared__ float s_rinv;
    int t = threadIdx.x;
    if ((t & 31) == 0) red[t >> 5] = ss;
    __syncthreads();
    if (t == 0) {
        float tot = 0.f;
        #pragma unroll
        for (int i = 0; i < 8; ++i) tot += red[i];
        s_rinv = rsqrtf(tot / (float)Hdim + 1e-6f);
    }
    __syncthreads();
    return s_rinv;
}

// ---------------- aux kernels ----------------
__global__ void k_relu_normquant(const float* __restrict__ hs,
                                 const float* __restrict__ nw,
                                 const float* __restrict__ gsp) {
    int row = blockIdx.x;
    int t = threadIdx.x;
    const float4* src = reinterpret_cast<const float4*>(hs + (size_t)row * Hdim);
    float4* xdst = reinterpret_cast<float4*>(g_X + (size_t)row * Hdim);
    float v[16];
    float ss = 0.f;
    #pragma unroll
    for (int i = 0; i < 4; ++i) {
        float4 f = src[t * 4 + i];
        f.x = fmaxf(f.x, 0.f); f.y = fmaxf(f.y, 0.f);
        f.z = fmaxf(f.z, 0.f); f.w = fmaxf(f.w, 0.f);
        xdst[t * 4 + i] = f;
        v[i * 4 + 0] = f.x; v[i * 4 + 1] = f.y; v[i * 4 + 2] = f.z; v[i * 4 + 3] = f.w;
        ss += f.x * f.x + f.y * f.y + f.z * f.z + f.w * f.w;
    }
    float rinv = block_rms(ss);
    const float4* nwv = reinterpret_cast<const float4*>(nw);
    #pragma unroll
    for (int i = 0; i < 4; ++i) {
        float4 g = nwv[t * 4 + i];
        v[i * 4 + 0] *= rinv * g.x; v[i * 4 + 1] *= rinv * g.y;
        v[i * 4 + 2] *= rinv * g.z; v[i * 4 + 3] *= rinv * g.w;
    }
    quant16(v, gsp[0], g_A + (size_t)row * Hdim + t * 16);
}

__global__ void k_normquant(const float* __restrict__ nw,
                            const float* __restrict__ gsp) {
    int row = blockIdx.x;
    int t = threadIdx.x;
    const float4* src = reinterpret_cast<const float4*>(g_X + (size_t)row * Hdim);
    float v[16];
    float ss = 0.f;
    #pragma unroll
    for (int i = 0; i < 4; ++i) {
        float4 f = src[t * 4 + i];
        v[i * 4 + 0] = f.x; v[i * 4 + 1] = f.y; v[i * 4 + 2] = f.z; v[i * 4 + 3] = f.w;
        ss += f.x * f.x + f.y * f.y + f.z * f.z + f.w * f.w;
    }
    float rinv = block_rms(ss);
    const float4* nwv = reinterpret_cast<const float4*>(nw);
    #pragma unroll
    for (int i = 0; i < 4; ++i) {
        float4 g = nwv[t * 4 + i];
        v[i * 4 + 0] *= rinv * g.x; v[i * 4 + 1] *= rinv * g.y;
        v[i * 4 + 2] *= rinv * g.z; v[i * 4 + 3] *= rinv * g.w;
    }
    quant16(v, gsp[0], g_A + (size_t)row * Hdim + t * 16);
}

__global__ void k_quantw(const float* __restrict__ w,
                         const float* __restrict__ wgs) {
    int bid = blockIdx.x;
    int i = bid >> 12;
    size_t off = (size_t)bid * Hdim;
    const float4* src = reinterpret_cast<const float4*>(w + off);
    float gs = wgs[i];
    int t = threadIdx.x;
    float v[16];
    #pragma unroll
    for (int j = 0; j < 4; ++j) {
        float4 f = src[t * 4 + j];
        v[j * 4 + 0] = f.x; v[j * 4 + 1] = f.y; v[j * 4 + 2] = f.z; v[j * 4 + 3] = f.w;
    }
    quant16(v, gs, g_W + off + t * 16);
}

__global__ void k_out(const float* __restrict__ nw, float* __restrict__ out) {
    int row = blockIdx.x;
    int t = threadIdx.x;
    const float4* src = reinterpret_cast<const float4*>(g_X + (size_t)row * Hdim);
    float4 vv[4];
    float ss = 0.f;
    #pragma unroll
    for (int i = 0; i < 4; ++i) {
        float4 f = src[t * 4 + i];
        vv[i] = f;
        ss += f.x * f.x + f.y * f.y + f.z * f.z + f.w * f.w;
    }
    float rinv = block_rms(ss);
    const float4* nwv = reinterpret_cast<const float4*>(nw);
    float4* dst = reinterpret_cast<float4*>(out + (size_t)row * Hdim);
    #pragma unroll
    for (int i = 0; i < 4; ++i) {
        float4 g = nwv[t * 4 + i];
        float4 r;
        r.x = vv[i].x * rinv * g.x; r.y = vv[i].y * rinv * g.y;
        r.z = vv[i].z * rinv * g.z; r.w = vv[i].w * rinv * g.w;
        dst[t * 4 + i] = r;
    }
}

// ======== mma.sync bf16 GEMM: X[M,N] += alpha * A[M,K] @ B[N,K]^T ========
// Tile 128x128xBK64, 3-stage cp.async pipeline, SW128-swizzled smem,
// 8 warps as 2x4 (warp tile 64x32), 2 CTAs/SM.
// One __syncthreads per K-iter; cp.async for stage kt+2 issued BEFORE compute(kt).
#define GBM 128
#define GBN 128
#define GBK 64
#define NSTAGE 3
#define TILE_B (GBM * 128)             // 16384 B (one operand, one stage)
#define STAGE_B (2 * TILE_B)           // 32768
#define GEMM_SMEM (NSTAGE * STAGE_B)   // 98304

__device__ __forceinline__ void cp16(uint32_t s, const void* g) {
    asm volatile("cp.async.cg.shared.global [%0], [%1], 16;\n" :: "r"(s), "l"(g));
}
__device__ __forceinline__ void ldmx4(uint32_t (&r)[4], uint32_t addr) {
    asm volatile("ldmatrix.sync.aligned.m8n8.x4.shared.b16 {%0,%1,%2,%3}, [%4];\n"
                 : "=r"(r[0]), "=r"(r[1]), "=r"(r[2]), "=r"(r[3]) : "r"(addr));
}
__device__ __forceinline__ void mma16816(float (&d)[4], const uint32_t (&a)[4],
                                         uint32_t b0, uint32_t b1) {
    asm volatile("mma.sync.aligned.m16n8k16.row.col.f32.bf16.bf16.f32 "
                 "{%0,%1,%2,%3}, {%4,%5,%6,%7}, {%8,%9}, {%0,%1,%2,%3};\n"
                 : "+f"(d[0]), "+f"(d[1]), "+f"(d[2]), "+f"(d[3])
                 : "r"(a[0]), "r"(a[1]), "r"(a[2]), "r"(a[3]), "r"(b0), "r"(b1));
}

__global__ __launch_bounds__(256, 2)
void k_gemm(int wi, const float* __restrict__ agp, const float* __restrict__ wgp) {
    extern __shared__ __align__(1024) char smem[];
    const uint32_t sbase = (uint32_t)__cvta_generic_to_shared(smem);

    const int tid = threadIdx.x;
    const int lane = tid & 31;
    const int wid = tid >> 5;
    const int wr = wid >> 2;            // 0..1  (64 rows each)
    const int wc = wid & 3;             // 0..3  (32 cols each)
    const int bm = blockIdx.y, bn = blockIdx.x;
    const int K = Hdim, N = Hdim;

    const __nv_bfloat16* Ag = g_A + (size_t)(bm * GBM) * K;
    const __nv_bfloat16* Bg = g_W + (size_t)wi * Hdim * Hdim + (size_t)(bn * GBN) * K;

    // ---- gmem->smem mapping: tid -> (row r0 + 32i, 16B segment), SW128 swizzle
    const int r0 = tid >> 3;                        // 0..31
    const int seg = tid & 7;                        // 16B segment in 128B row
    const uint32_t swoff = (uint32_t)(r0 * 128) + (uint32_t)((seg * 16) ^ ((r0 & 7) << 4));
    const __nv_bfloat16* gA = Ag + (size_t)r0 * K + seg * 8;
    const __nv_bfloat16* gB = Bg + (size_t)r0 * K + seg * 8;

    // ---- ldmatrix address precompute (swizzle XOR folded)
    const uint32_t aRowB = (uint32_t)((wr * 64 + (lane & 15)) * 128);
    const uint32_t aXor = (uint32_t)((lane & 7) << 4);
    const uint32_t aColB = (uint32_t)((lane >> 4) * 16);
    const uint32_t bRowB = (uint32_t)((wc * 32 + (lane & 7) + ((lane >> 4) & 1) * 8) * 128);
    const uint32_t bXor = aXor;
    const uint32_t bColB = (uint32_t)(((lane >> 3) & 1) * 16);

    float acc[4][4][4];
    #pragma unroll
    for (int mi = 0; mi < 4; ++mi)
        #pragma unroll
        for (int ni = 0; ni < 4; ++ni)
            #pragma unroll
            for (int j = 0; j < 4; ++j) acc[mi][ni][j] = 0.f;

    const int nk = K / GBK;   // 64

    auto load_stage = [&](int s, int kt) {
        uint32_t stA = sbase + s * STAGE_B;
        uint32_t stB = stA + TILE_B;
        const __nv_bfloat16* pA = gA + kt * GBK;
        const __nv_bfloat16* pB = gB + kt * GBK;
        #pragma unroll
        for (int i = 0; i < 4; ++i)
            cp16(stA + swoff + i * 4096, pA + (size_t)(i * 32) * K);
        #pragma unroll
        for (int i = 0; i < 4; ++i)
            cp16(stB + swoff + i * 4096, pB + (size_t)(i * 32) * K);
        asm volatile("cp.async.commit_group;\n");
    };

    load_stage(0, 0);
    load_stage(1, 1);

    int s = 0;          // stage being computed
    int sl = 2;         // stage to load next
    #pragma unroll 1
    for (int kt = 0; kt < nk; ++kt) {
        if (kt == nk - 1) asm volatile("cp.async.wait_group 0;\n" ::: "memory");
        else              asm volatile("cp.async.wait_group 1;\n" ::: "memory");
        __syncthreads();
        // issue loads for stage kt+2 FIRST so compute covers their latency.
        // Safe: slot sl == (kt-1)%3 was fully consumed before the barrier above.
        if (kt + 2 < nk) {
            load_stage(sl, kt + 2);
            if (++sl == NSTAGE) sl = 0;
        }

        uint32_t stA = sbase + s * STAGE_B;
        uint32_t stB = stA + TILE_B;
        #pragma unroll
        for (int kk = 0; kk < GBK; kk += 16) {
            uint32_t b[2][4];
            #pragma unroll
            for (int ng = 0; ng < 2; ++ng)
                ldmx4(b[ng], stB + bRowB + ng * 2048 + ((kk * 2 + bColB) ^ bXor));
            #pragma unroll
            for (int mi = 0; mi < 4; ++mi) {
                uint32_t a[4];
                ldmx4(a, stA + aRowB + mi * 2048 + ((kk * 2 + aColB) ^ aXor));
                #pragma unroll
                for (int ni = 0; ni < 4; ++ni)
                    mma16816(acc[mi][ni], a,
                             b[ni >> 1][(ni & 1) * 2], b[ni >> 1][(ni & 1) * 2 + 1]);
            }
        }
        if (++s == NSTAGE) s = 0;
    }

    // epilogue: X += alpha * acc  (fused residual add)
    const float alpha = 1.0f / (wgp[0] * agp[0]);
    float* C = g_X;
    #pragma unroll
    for (int mi = 0; mi < 4; ++mi) {
        #pragma unroll
        for (int ni = 0; ni < 4; ++ni) {
            int row = bm * GBM + wr * 64 + mi * 16 + (lane >> 2);
            int col = bn * GBN + wc * 32 + ni * 8 + (lane & 3) * 2;
            float2* p0 = reinterpret_cast<float2*>(&C[(size_t)row * N + col]);
            float2 c0 = *p0;
            c0.x += alpha * acc[mi][ni][0];
            c0.y += alpha * acc[mi][ni][1];
            *p0 = c0;
            float2* p1 = reinterpret_cast<float2*>(&C[(size_t)(row + 8) * N + col]);
            float2 c1 = *p1;
            c1.x += alpha * acc[mi][ni][2];
            c1.y += alpha * acc[mi][ni][3];
            *p1 = c1;
        }
    }
}

// ---------------- launch ----------------
extern "C" void kernel_launch(void* const* d_in, const int* in_sizes, int n_in,
                              void* d_out, int out_size) {
    const float* hs  = (const float*)d_in[0];  // [T, H]
    const float* nw  = (const float*)d_in[1];  // [4, H]
    const float* w   = (const float*)d_in[2];  // [3, H, H]
    const float* ags = (const float*)d_in[3];  // [3]
    const float* wgs = (const float*)d_in[4];  // [3]
    float* out = (float*)d_out;                // [T, H]

    cudaFuncSetAttribute(k_gemm, cudaFuncAttributeMaxDynamicSharedMemorySize, GEMM_SMEM);

    k_quantw<<<3 * Hdim, 256>>>(w, wgs);
    k_relu_normquant<<<Tdim, 256>>>(hs, nw, ags);

    dim3 gg(Hdim / GBN, Tdim / GBM);   // (32, 64)
    for (int i = 0; i < 3; ++i) {
        k_gemm<<<gg, 256, GEMM_SMEM>>>(i, ags + i, wgs + i);
        if (i < 2) k_normquant<<<Tdim, 256>>>(nw + (size_t)(i + 1) * Hdim, ags + i + 1);
    }
    k_out<<<Tdim, 256>>>(nw + 3 * Hdim, out);
}